// round 7
// baseline (speedup 1.0000x reference)
#include <cuda_runtime.h>

// Problem constants (fixed shapes from the reference)
#define BB 256      // batch
#define NN 73728    // variables
#define KK 8        // messages per variable
#define NT 32       // n-tile per block in K2

// Scratch: transposed check matrix, (N, B) row-major. 75.5 MB, static device bss.
__device__ __align__(16) float g_checkT[(size_t)NN * BB];

// ---------------------------------------------------------------------------
// K1: tiled transpose  check (B,N) -> checkT (N,B).
// Vector LDG.128 / STG.128 on gmem; scalar smem ops (conflict-free, no 16B
// alignment hazard with the 33-float row padding).
// check is read once -> evict-first (__ldcs). checkT stores keep default
// policy so they seed L2 for K2's gathers.
// ---------------------------------------------------------------------------
__global__ void __launch_bounds__(256) transpose_check_kernel(
    const float* __restrict__ check)
{
    __shared__ float tile[32][33];
    const int n0 = blockIdx.x * 32;
    const int b0 = blockIdx.y * 32;
    const int tx = threadIdx.x;   // 0..7
    const int ty = threadIdx.y;   // 0..31

    const float4 in4 = __ldcs((const float4*)&check[(size_t)(b0 + ty) * NN + (n0 + 4 * tx)]);
    tile[ty][4 * tx + 0] = in4.x;   // bank (ty + 4tx + c) % 32: all distinct
    tile[ty][4 * tx + 1] = in4.y;
    tile[ty][4 * tx + 2] = in4.z;
    tile[ty][4 * tx + 3] = in4.w;
    __syncthreads();

    float4 o;
    o.x = tile[4 * tx + 0][ty];     // bank (4tx + c + ty) % 32: all distinct
    o.y = tile[4 * tx + 1][ty];
    o.z = tile[4 * tx + 2][ty];
    o.w = tile[4 * tx + 3][ty];
    *(float4*)&g_checkT[(size_t)(n0 + ty) * BB + (b0 + 4 * tx)] = o;
}

// ---------------------------------------------------------------------------
// K2: gather-sum + fused back-transpose, float4 gather, 512 threads/block.
// checkT gathers use default/LDG (cache-friendly, L2-resident working set);
// llr/out are pure streams -> __ldcs/__stcs (evict-first) so they do not
// evict checkT lines from L2 between gather re-reads.
// Phase 1: thread (sub = tid/64 in 0..7, bq = tid%64). For its 4 n-values,
//          sums 8 float4 gathers each (LDG.128; 64 threads span a 1KB row).
// Phase 2: warp w writes b-rows [w*16, w*16+16); lanes sweep n -> coalesced.
// ---------------------------------------------------------------------------
__global__ void __launch_bounds__(512) gather_sum_kernel(
    const float* __restrict__ llr,
    const int* __restrict__ var_idx,        // (N, K) int32, -1 = invalid
    float* __restrict__ out)
{
    __shared__ int s_idx[NT * KK];                       // 1 KB
    __shared__ __align__(16) float s_sum[NT][260];       // 33.3 KB, row = 1040B (16B-divisible)

    const int n0  = blockIdx.x * NT;
    const int tid = threadIdx.x;              // 0..511

    // index tile: 32 n * 8 k = 256 int32, first 256 threads load, coalesced
    if (tid < NT * KK) s_idx[tid] = __ldg(&var_idx[(size_t)n0 * KK + tid]);
    __syncthreads();

    const int sub = tid >> 6;                 // 0..7  (n interleave)
    const int bq  = tid & 63;                 // float4 index over b
    const float4* __restrict__ cT4 = (const float4*)g_checkT;

    #pragma unroll
    for (int i = 0; i < NT / 8; i++) {        // 4 iterations
        const int nl = i * 8 + sub;
        int jj[KK];
        #pragma unroll
        for (int k = 0; k < KK; k++) jj[k] = s_idx[nl * KK + k];

        float4 s = make_float4(0.f, 0.f, 0.f, 0.f);
        #pragma unroll
        for (int k = 0; k < KK; k++) {
            if (jj[k] >= 0) {
                const float4 v = __ldg(&cT4[(size_t)jj[k] * (BB / 4) + bq]);
                s.x += v.x; s.y += v.y; s.z += v.z; s.w += v.w;
            }
        }
        // STS.128 at word 260*nl + 4*bq: 16B-aligned, consecutive bq -> conflict-free
        *(float4*)&s_sum[nl][4 * bq] = s;
    }
    __syncthreads();

    // Phase 2: transposed writeback. lane -> n (coalesced gmem), streaming hints.
    const int lane = tid & 31;
    const int w    = tid >> 5;                // 0..15
    const int n    = n0 + lane;
    #pragma unroll 4
    for (int bi = 0; bi < 16; bi++) {
        const int b = w * 16 + bi;
        const size_t g = (size_t)b * NN + n;
        const float v = __ldcs(&llr[g]) + s_sum[lane][b];
        __stcs(&out[g], v);
    }
}

extern "C" void kernel_launch(void* const* d_in, const int* in_sizes, int n_in,
                              void* d_out, int out_size)
{
    const float* llr   = (const float*)d_in[0];   // (B, N) f32
    const float* check = (const float*)d_in[1];   // (B, N) f32
    const int*   vidx  = (const int*)d_in[2];     // (N, K) i32
    float*       out   = (float*)d_out;           // (B, N) f32
    (void)in_sizes; (void)n_in; (void)out_size;

    // K1: transpose check -> g_checkT
    dim3 tb(8, 32);
    dim3 tg(NN / 32, BB / 32);
    transpose_check_kernel<<<tg, tb>>>(check);

    // K2: gather + sum + fused output transpose
    gather_sum_kernel<<<NN / NT, 512>>>(llr, vidx, out);
}

// round 8
// speedup vs baseline: 1.2960x; 1.2960x over previous
#include <cuda_runtime.h>

// Problem constants (fixed shapes from the reference)
#define BB 256      // batch
#define NN 73728    // variables
#define KK 8        // messages per variable
#define NT 32       // n-tile per block in K2

// Scratch: transposed check matrix, (N, B) row-major. 75.5 MB, static device bss.
__device__ __align__(16) float g_checkT[(size_t)NN * BB];

// ---------------------------------------------------------------------------
// K1: tiled transpose  check (B,N) -> checkT (N,B), 128n x 32b per block.
// Each thread issues 4 independent LDG.128 and 4 independent STG.128 (MLP=4)
// to cover DRAM latency; scalar smem ops through 4 padded 32x33 tiles keep
// the conflict-free bank pattern and avoid the 132B-row alignment trap.
// block (8,32): tx = float4 column, ty = row.
// ---------------------------------------------------------------------------
__global__ void __launch_bounds__(256) transpose_check_kernel(
    const float* __restrict__ check)
{
    __shared__ float tile[4][32][33];
    const int n0 = blockIdx.x * 128;
    const int b0 = blockIdx.y * 32;
    const int tx = threadIdx.x;   // 0..7
    const int ty = threadIdx.y;   // 0..31

    float4 in4[4];
    #pragma unroll
    for (int t = 0; t < 4; t++) {
        in4[t] = *(const float4*)&check[(size_t)(b0 + ty) * NN + (n0 + 32 * t + 4 * tx)];
    }
    #pragma unroll
    for (int t = 0; t < 4; t++) {
        tile[t][ty][4 * tx + 0] = in4[t].x;   // bank (ty + 4tx + c) % 32: distinct
        tile[t][ty][4 * tx + 1] = in4[t].y;
        tile[t][ty][4 * tx + 2] = in4[t].z;
        tile[t][ty][4 * tx + 3] = in4[t].w;
    }
    __syncthreads();

    #pragma unroll
    for (int t = 0; t < 4; t++) {
        float4 o;
        o.x = tile[t][4 * tx + 0][ty];        // bank (4tx + c + ty) % 32: distinct
        o.y = tile[t][4 * tx + 1][ty];
        o.z = tile[t][4 * tx + 2][ty];
        o.w = tile[t][4 * tx + 3][ty];
        *(float4*)&g_checkT[(size_t)(n0 + 32 * t + ty) * BB + (b0 + 4 * tx)] = o;
    }
}

// ---------------------------------------------------------------------------
// K2: gather-sum + fused back-transpose, float4 gather, 512 threads/block.
// (Exact R6 configuration -- best measured: 74.3us.)
// Phase 1: thread (sub = tid/64 in 0..7, bq = tid%64). For its 4 n-values,
//          sums 8 float4 gathers each (LDG.128; 64 threads span a 1KB row).
// Phase 2: warp w writes b-rows [w*16, w*16+16); lanes sweep n -> coalesced.
// ---------------------------------------------------------------------------
__global__ void __launch_bounds__(512) gather_sum_kernel(
    const float* __restrict__ llr,
    const int* __restrict__ var_idx,        // (N, K) int32, -1 = invalid
    float* __restrict__ out)
{
    __shared__ int s_idx[NT * KK];                       // 1 KB
    __shared__ __align__(16) float s_sum[NT][260];       // 33.3 KB, row = 1040B (16B-divisible)

    const int n0  = blockIdx.x * NT;
    const int tid = threadIdx.x;              // 0..511

    // index tile: 32 n * 8 k = 256 int32, first 256 threads load, coalesced
    if (tid < NT * KK) s_idx[tid] = var_idx[(size_t)n0 * KK + tid];
    __syncthreads();

    const int sub = tid >> 6;                 // 0..7  (n interleave)
    const int bq  = tid & 63;                 // float4 index over b
    const float4* __restrict__ cT4 = (const float4*)g_checkT;

    #pragma unroll
    for (int i = 0; i < NT / 8; i++) {        // 4 iterations
        const int nl = i * 8 + sub;
        int jj[KK];
        #pragma unroll
        for (int k = 0; k < KK; k++) jj[k] = s_idx[nl * KK + k];

        float4 s = make_float4(0.f, 0.f, 0.f, 0.f);
        #pragma unroll
        for (int k = 0; k < KK; k++) {
            if (jj[k] >= 0) {
                const float4 v = __ldg(&cT4[(size_t)jj[k] * (BB / 4) + bq]);
                s.x += v.x; s.y += v.y; s.z += v.z; s.w += v.w;
            }
        }
        // STS.128 at word 260*nl + 4*bq: 16B-aligned, consecutive bq -> conflict-free
        *(float4*)&s_sum[nl][4 * bq] = s;
    }
    __syncthreads();

    // Phase 2: transposed writeback. lane -> n (coalesced gmem).
    const int lane = tid & 31;
    const int w    = tid >> 5;                // 0..15
    const int n    = n0 + lane;
    #pragma unroll 4
    for (int bi = 0; bi < 16; bi++) {
        const int b = w * 16 + bi;
        const size_t g = (size_t)b * NN + n;
        out[g] = llr[g] + s_sum[lane][b];
    }
}

extern "C" void kernel_launch(void* const* d_in, const int* in_sizes, int n_in,
                              void* d_out, int out_size)
{
    const float* llr   = (const float*)d_in[0];   // (B, N) f32
    const float* check = (const float*)d_in[1];   // (B, N) f32
    const int*   vidx  = (const int*)d_in[2];     // (N, K) i32
    float*       out   = (float*)d_out;           // (B, N) f32
    (void)in_sizes; (void)n_in; (void)out_size;

    // K1: transpose check -> g_checkT (128n x 32b tiles)
    dim3 tb(8, 32);
    dim3 tg(NN / 128, BB / 32);
    transpose_check_kernel<<<tg, tb>>>(check);

    // K2: gather + sum + fused output transpose
    gather_sum_kernel<<<NN / NT, 512>>>(llr, vidx, out);
}

// round 11
// speedup vs baseline: 1.4649x; 1.1304x over previous
#include <cuda_runtime.h>

// Problem constants (fixed shapes from the reference)
#define BB 256      // batch
#define NN 73728    // variables
#define KK 8        // messages per variable
#define NT 32       // n-tile per block in K2
#define BH 128      // batch half processed per K2 pass

// Scratch: transposed check matrix, stored as (2, N, 128): two b-halves,
// each (N, 128) row-major. 75.5 MB total, static device bss.
__device__ __align__(16) float g_checkT[(size_t)2 * NN * BH];

// ---------------------------------------------------------------------------
// K1: tiled transpose  check (B,N) -> checkT (2, N, 128), 128n x 32b per block.
// Each thread: 4 independent LDG.128 + 4 independent STG.128 (MLP=4).
// Scalar smem ops through 4 padded 32x33 tiles (conflict-free, alignment-safe).
// block (8,32): tx = float4 column, ty = row.
// ---------------------------------------------------------------------------
__global__ void __launch_bounds__(256) transpose_check_kernel(
    const float* __restrict__ check)
{
    __shared__ float tile[4][32][33];
    const int n0 = blockIdx.x * 128;
    const int b0 = blockIdx.y * 32;          // multiple of 32 -> single half
    const int tx = threadIdx.x;   // 0..7
    const int ty = threadIdx.y;   // 0..31

    float4 in4[4];
    #pragma unroll
    for (int t = 0; t < 4; t++) {
        in4[t] = *(const float4*)&check[(size_t)(b0 + ty) * NN + (n0 + 32 * t + 4 * tx)];
    }
    #pragma unroll
    for (int t = 0; t < 4; t++) {
        tile[t][ty][4 * tx + 0] = in4[t].x;   // bank (ty + 4tx + c) % 32: distinct
        tile[t][ty][4 * tx + 1] = in4[t].y;
        tile[t][ty][4 * tx + 2] = in4[t].z;
        tile[t][ty][4 * tx + 3] = in4[t].w;
    }
    __syncthreads();

    const int h  = b0 >> 7;                   // which half
    const int bl = (b0 & (BH - 1)) + 4 * tx;  // b offset within half
    float* __restrict__ cth = g_checkT + (size_t)h * NN * BH;
    #pragma unroll
    for (int t = 0; t < 4; t++) {
        float4 o;
        o.x = tile[t][4 * tx + 0][ty];        // bank (4tx + c + ty) % 32: distinct
        o.y = tile[t][4 * tx + 1][ty];
        o.z = tile[t][4 * tx + 2][ty];
        o.w = tile[t][4 * tx + 3][ty];
        *(float4*)&cth[(size_t)(n0 + 32 * t + ty) * BH + bl] = o;
    }
}

// ---------------------------------------------------------------------------
// K2: gather-sum + fused back-transpose over ONE batch half (128 b).
// Gather working set = 37.7MB -> L2-resident, so the 8x random re-reads hit L2.
// Phase 1: thread (sub = tid/32 in 0..7, bq = tid%32). For its 4 n-values,
//          sums 8 float4 gathers each (LDG.128; 32 threads span a 512B row).
// Phase 2: warp w writes b-rows [w*16, w*16+16) of this half; lanes sweep n.
// Two sequential launches (h=0, h=1) on the same stream.
// ---------------------------------------------------------------------------
__global__ void __launch_bounds__(256) gather_sum_kernel(
    const float* __restrict__ llr,
    const int* __restrict__ var_idx,        // (N, K) int32, -1 = invalid
    float* __restrict__ out,
    const int h)                             // batch half: 0 or 1
{
    __shared__ int s_idx[NT * KK];                       // 1 KB
    __shared__ __align__(16) float s_sum[NT][BH + 4];    // 32 x 132 = 16.9 KB, row 528B

    const int n0  = blockIdx.x * NT;
    const int tid = threadIdx.x;              // 0..255

    // index tile: 32 n * 8 k = 256 int32 -> one per thread, coalesced
    s_idx[tid] = var_idx[(size_t)n0 * KK + tid];
    __syncthreads();

    const int sub = tid >> 5;                 // 0..7  (n interleave)
    const int bq  = tid & 31;                 // float4 index over this half's b
    const float4* __restrict__ cT4 =
        (const float4*)(g_checkT + (size_t)h * NN * BH);

    #pragma unroll
    for (int i = 0; i < NT / 8; i++) {        // 4 iterations
        const int nl = i * 8 + sub;
        int jj[KK];
        #pragma unroll
        for (int k = 0; k < KK; k++) jj[k] = s_idx[nl * KK + k];

        float4 s = make_float4(0.f, 0.f, 0.f, 0.f);
        #pragma unroll
        for (int k = 0; k < KK; k++) {
            if (jj[k] >= 0) {
                const float4 v = __ldg(&cT4[(size_t)jj[k] * (BH / 4) + bq]);
                s.x += v.x; s.y += v.y; s.z += v.z; s.w += v.w;
            }
        }
        // STS.128 at word 132*nl + 4*bq: 16B-aligned, consecutive bq -> conflict-free
        *(float4*)&s_sum[nl][4 * bq] = s;
    }
    __syncthreads();

    // Phase 2: transposed writeback for this half. lane -> n (coalesced gmem).
    const int lane = tid & 31;
    const int w    = tid >> 5;                // 0..7
    const int n    = n0 + lane;
    #pragma unroll 4
    for (int bi = 0; bi < BH / 8; bi++) {     // 16 b-rows per warp
        const int bl = w * (BH / 8) + bi;     // b within half
        const size_t g = (size_t)(h * BH + bl) * NN + n;
        out[g] = llr[g] + s_sum[lane][bl];
    }
}

extern "C" void kernel_launch(void* const* d_in, const int* in_sizes, int n_in,
                              void* d_out, int out_size)
{
    const float* llr   = (const float*)d_in[0];   // (B, N) f32
    const float* check = (const float*)d_in[1];   // (B, N) f32
    const int*   vidx  = (const int*)d_in[2];     // (N, K) i32
    float*       out   = (float*)d_out;           // (B, N) f32
    (void)in_sizes; (void)n_in; (void)out_size;

    // K1: transpose check -> g_checkT (split-half layout)
    dim3 tb(8, 32);
    dim3 tg(NN / 128, BB / 32);
    transpose_check_kernel<<<tg, tb>>>(check);

    // K2: gather + sum + fused output transpose, one batch half per launch.
    // Same stream -> halves run sequentially, keeping each 37.7MB gather
    // working set L2-resident.
    gather_sum_kernel<<<NN / NT, 256>>>(llr, vidx, out, 0);
    gather_sum_kernel<<<NN / NT, 256>>>(llr, vidx, out, 1);
}